// round 16
// baseline (speedup 1.0000x reference)
#include <cuda_runtime.h>
#include <cuda_fp16.h>
#include <cstdint>
#include <cstddef>

// Problem constants
#define NEMB   1024
#define EDIM   256
#define BATCH  8
#define HWL    4096
#define NROWS  32768
#define MT     128
#define NBLK   256
#define NCB    8             // 8 code blocks of 128
#define CAP    4096
#define NTHR   512

// smem byte offsets
#define SM_A     0           // 128 rows * 512 B (fp16, XOR-swizzled 16B units)
#define SM_B     65536       // 2 * 128 codes * 512 B
#define BBYTES   65536
#define SM_E2    196608      // 2*128 floats
#define SM_Z2    197632
#define SM_CR    198144
#define SM_EP    198656
#define SM_V     199168      // 4*128 floats
#define SM_BEST  201216      // 128 u64
#define SM_CAND  202240      // 4096 u32
#define SM_CNT   218624
#define SM_TOTAL 218640

// Scratch
__device__ float  g_zf[NROWS*EDIM];   // z transposed (N, D) fp32
__device__ uint4  g_zh[NROWS*32];     // fp16 zhat rows (32x16B = 256 dims)
__device__ uint4  g_eh[NEMB*32];      // fp16 ehat rows (e * 1024)
__device__ float  g_e2[NEMB];
__device__ float  g_z2[NROWS];
__device__ float  g_cr[NROWS];        // amax/512
__device__ float  g_eps[NROWS];       // HARD screening bound
__device__ int    g_idx[NROWS];
__device__ double g_partial[NBLK];

// ---------------- helpers ----------------
__device__ __forceinline__ uint32_t smem_u32(const void* p) {
    uint32_t a;
    asm("{ .reg .u64 t; cvta.to.shared.u64 t, %1; cvt.u32.u64 %0, t; }" : "=r"(a) : "l"(p));
    return a;
}
__device__ __forceinline__ void cpa16(uint32_t dst, const void* src) {
    asm volatile("cp.async.cg.shared.global [%0], [%1], 16;" :: "r"(dst), "l"(src));
}
__device__ __forceinline__ void cpa4(uint32_t dst, const void* src) {
    asm volatile("cp.async.ca.shared.global [%0], [%1], 4;" :: "r"(dst), "l"(src));
}
#define CP_COMMIT() asm volatile("cp.async.commit_group;" ::: "memory")
#define CP_WAIT1()  asm volatile("cp.async.wait_group 1;" ::: "memory")
#define CP_WAIT0()  asm volatile("cp.async.wait_group 0;" ::: "memory")

#define LDMX4(r0, r1, r2, r3, addr) \
    asm volatile("ldmatrix.sync.aligned.m8n8.x4.shared.b16 {%0,%1,%2,%3}, [%4];" \
        : "=r"(r0), "=r"(r1), "=r"(r2), "=r"(r3) : "r"(addr))

__device__ __forceinline__ void mma16816(float* d, const uint32_t* a, const uint32_t* b) {
    asm volatile("mma.sync.aligned.m16n8k16.row.col.f32.f16.f16.f32 "
        "{%0,%1,%2,%3}, {%4,%5,%6,%7}, {%8,%9}, {%0,%1,%2,%3};"
        : "+f"(d[0]), "+f"(d[1]), "+f"(d[2]), "+f"(d[3])
        : "r"(a[0]), "r"(a[1]), "r"(a[2]), "r"(a[3]), "r"(b[0]), "r"(b[1]));
}

// exact fp32 distance — IDENTICAL pipeline to the passing R2/R7/R11/R14/R15 kernels
__device__ __forceinline__ float exact_dist(int nrow, int k, float z2r,
                                            const float* __restrict__ cb) {
    const float* zr = g_zf + (size_t)nrow*EDIM;
    const float* er = cb   + (size_t)k*EDIM;
    float s0 = 0.f, s1 = 0.f;
    #pragma unroll 8
    for (int d = 0; d < EDIM; d += 2) {
        s0 += zr[d]   * er[d];
        s1 += zr[d+1] * er[d+1];
    }
    return (z2r + g_e2[k]) - 2.f*(s0 + s1);
}

// ---------------------------------------------------------------------------
// Kernel A: transpose z (B, D, HWL) -> zf (B*HWL, D)
// ---------------------------------------------------------------------------
__global__ void vq_transpose(const float* __restrict__ z) {
    __shared__ float tile[32][33];
    int b = blockIdx.z, d0 = blockIdx.y << 5, s0 = blockIdx.x << 5;
    int tx = threadIdx.x, ty = threadIdx.y;
    const float* src = z + ((size_t)b*EDIM + d0)*HWL + s0;
    #pragma unroll
    for (int i = 0; i < 32; i += 8)
        tile[ty+i][tx] = src[(size_t)(ty+i)*HWL + tx];
    __syncthreads();
    float* dst = g_zf + ((size_t)b*HWL + s0)*EDIM + d0;
    #pragma unroll
    for (int i = 0; i < 32; i += 8)
        dst[(size_t)(ty+i)*EDIM + tx] = tile[tx][ty+i];
}

// ---------------------------------------------------------------------------
// Kernel B: codebook row norms (double accumulate -> correctly rounded fp32)
// ---------------------------------------------------------------------------
__global__ void vq_e2(const float* __restrict__ cb) {
    int k = blockIdx.x * blockDim.x + threadIdx.x;
    if (k < NEMB) {
        const float* row = cb + (size_t)k*EDIM;
        double s = 0.0;
        for (int d = 0; d < EDIM; d++) { double v = row[d]; s += v*v; }
        g_e2[k] = (float)s;
    }
}

// ---------------------------------------------------------------------------
// Kernel B2: pack codebook to fp16 ehat = 1024*e
// ---------------------------------------------------------------------------
__global__ __launch_bounds__(256)
void vq_packe(const float* __restrict__ cb) {
    int row = blockIdx.x*8 + (threadIdx.x >> 5);
    int lane = threadIdx.x & 31;
    const float* er = cb + (size_t)row*EDIM + lane*8;
    __half2 h[4];
    #pragma unroll
    for (int p = 0; p < 4; p++)
        h[p] = __floats2half2_rn(er[2*p]*1024.f, er[2*p+1]*1024.f);
    g_eh[row*32 + lane] = *(uint4*)h;
}

// ---------------------------------------------------------------------------
// Kernel B3: pack z rows to fp16 zhat = z/amax + per-row stats (proven R15)
// ---------------------------------------------------------------------------
__global__ __launch_bounds__(256)
void vq_packz() {
    __shared__ float zt[32*257];
    int t = threadIdx.x;
    int rows = blockIdx.x * 32;
    for (int i = t; i < 32*64; i += 256) {
        int r = i >> 6, c4 = (i & 63) << 2;
        float4 v = *(const float4*)(g_zf + (size_t)(rows + r)*EDIM + c4);
        float* d = zt + r*257 + c4;
        d[0] = v.x; d[1] = v.y; d[2] = v.z; d[3] = v.w;
    }
    __syncthreads();
    if (t < 64) {
        int r = t >> 1, h = t & 1;
        int row = rows + r;
        const float* p = zt + r*257 + h*128;
        float s = 0.f, amax = 0.f;
        #pragma unroll 8
        for (int d = 0; d < 128; d++) {
            float v = p[d];
            s += v*v;
            amax = fmaxf(amax, fabsf(v));
        }
        float so = __shfl_xor_sync(0xffffffffu, s, 1);
        amax = fmaxf(amax, __shfl_xor_sync(0xffffffffu, amax, 1));
        if (!h) {
            float z2 = s + so;                        // R2 ordering
            g_z2[row] = z2;
            g_cr[row] = amax * (1.f/512.f);           // 2*amax/1024
            g_eps[row] = sqrtf(z2)*6.3e-5f + amax*4e-5f + 2e-4f;
        }
        float scale = (amax > 0.f) ? (1.f/amax) : 0.f;
        #pragma unroll 4
        for (int wq = 0; wq < 16; wq++) {
            const float* q = p + wq*8;
            __half2 hh[4];
            #pragma unroll
            for (int k = 0; k < 4; k++)
                hh[k] = __floats2half2_rn(q[2*k]*scale, q[2*k+1]*scale);
            g_zh[row*32 + h*16 + wq] = *(uint4*)hh;
        }
    }
}

// ---------------------------------------------------------------------------
// Stagers (proven R15 swizzle): unit u of row r stored at u ^ (r&7)
// ---------------------------------------------------------------------------
__device__ __forceinline__ void stageA(uint32_t sb, int n0, int t) {
    const uint4* src = g_zh + (size_t)n0*32;
    #pragma unroll
    for (int j = 0; j < 8; j++) {
        int i = t + j*NTHR;                // 0..4095
        int r = i >> 5, u = i & 31;
        cpa16(sb + SM_A + (uint32_t)(r*512 + ((u ^ (r & 7)) << 4)), src + r*32 + u);
    }
}
__device__ __forceinline__ void loadB(uint32_t sb, int cb, int t) {
    int buf = cb & 1;
    const uint4* src = g_eh + cb*128*32;
    uint32_t dst = sb + SM_B + buf*BBYTES;
    #pragma unroll
    for (int j = 0; j < 8; j++) {
        int i = t + j*NTHR;                // 0..4095
        int r = i >> 5, u = i & 31;
        cpa16(dst + (uint32_t)(r*512 + ((u ^ (r & 7)) << 4)), src + r*32 + u);
    }
    if (t < 128) cpa4(sb + SM_E2 + buf*512 + t*4, g_e2 + cb*128 + t);
    CP_COMMIT();
}

// ---------------------------------------------------------------------------
// Kernel C: fp16 mma.sync + running-min screening + exact fp32 rescore.
// 512 threads = 16 warps (4 row x 4 col); warp tile 32 rows x 32 codes;
// register double-buffered ldmatrix fragments.
// ---------------------------------------------------------------------------
__global__ __launch_bounds__(NTHR, 1)
void vq_screen(const float* __restrict__ cb, float* __restrict__ out_idx, int write_idx) {
    extern __shared__ char smc[];
    uint32_t sb = smem_u32(smc);
    float* z2s  = (float*)(smc + SM_Z2);
    float* crs  = (float*)(smc + SM_CR);
    float* epss = (float*)(smc + SM_EP);
    float* V    = (float*)(smc + SM_V);
    unsigned long long* best = (unsigned long long*)(smc + SM_BEST);
    unsigned* cand = (unsigned*)(smc + SM_CAND);
    int* scnt = (int*)(smc + SM_CNT);

    const int t = threadIdx.x, lane = t & 31, w = t >> 5;
    const int rw = w & 3, cq = w >> 2;             // 4 row-warps x 4 col-warps
    const int la = lane & 7;
    const int g  = lane >> 2, q = lane & 3;
    const int n0 = blockIdx.x * MT;

    if (t < MT) {
        best[t] = ~0ull;
        z2s[t]  = g_z2[n0 + t];
        crs[t]  = g_cr[n0 + t];
        epss[t] = g_eps[n0 + t];
    }
    if (t < 4*MT) V[t] = 3.4e38f;
    if (t == 0) *scnt = 0;

    stageA(sb, n0, t);
    loadB(sb, 0, t);       // group0 = A + B0 + e2_0
    loadB(sb, 1, t);       // group1 = B1 + e2_1

    // ldmatrix per-lane geometry (proven R15)
    const int m4   = lane >> 3;
    const int arow = rw*32 + (m4 & 1)*8 + la;
    const int auo  = m4 >> 1;
    const int bco  = ((m4 >> 1) & 1)*8 + la;
    const int buo  = m4 & 1;
    const uint32_t aAbase = sb + SM_A + (uint32_t)arow*512;

    for (int cbk = 0; cbk < NCB; cbk++) {
        int buf = cbk & 1;
        if (cbk + 1 < NCB) CP_WAIT1(); else CP_WAIT0();
        __syncthreads();

        const uint32_t bBbase = sb + SM_B + buf*BBYTES;
        const float* e2c = (const float*)(smc + SM_E2 + buf*512);

        float d[2][4][4];
        #pragma unroll
        for (int mr = 0; mr < 2; mr++)
            #pragma unroll
            for (int nc = 0; nc < 4; nc++)
                #pragma unroll
                for (int u = 0; u < 4; u++) d[mr][nc][u] = 0.f;

        uint32_t a[2][2][4], b[2][4][2];
        // prologue: fragments for ks=0 into slot 0
        #pragma unroll
        for (int mr = 0; mr < 2; mr++) {
            uint32_t addr = aAbase + mr*16*512 + (uint32_t)((auo ^ la) << 4);
            LDMX4(a[0][mr][0], a[0][mr][1], a[0][mr][2], a[0][mr][3], addr);
        }
        #pragma unroll
        for (int p = 0; p < 2; p++) {
            int code = cq*32 + p*16 + bco;
            uint32_t addr = bBbase + (uint32_t)code*512 + (uint32_t)((buo ^ la) << 4);
            uint32_t r0, r1, r2, r3;
            LDMX4(r0, r1, r2, r3, addr);
            b[0][2*p][0] = r0;   b[0][2*p][1] = r1;
            b[0][2*p+1][0] = r2; b[0][2*p+1][1] = r3;
        }

        #pragma unroll
        for (int ks = 0; ks < 16; ks++) {
            const int cur = ks & 1, nxt = cur ^ 1;
            if (ks < 15) {   // prefetch ks+1 fragments while mma issues
                #pragma unroll
                for (int mr = 0; mr < 2; mr++) {
                    uint32_t addr = aAbase + mr*16*512
                                  + (uint32_t)(((2*(ks+1) + auo) ^ la) << 4);
                    LDMX4(a[nxt][mr][0], a[nxt][mr][1], a[nxt][mr][2], a[nxt][mr][3], addr);
                }
                #pragma unroll
                for (int p = 0; p < 2; p++) {
                    int code = cq*32 + p*16 + bco;
                    uint32_t addr = bBbase + (uint32_t)code*512
                                  + (uint32_t)(((2*(ks+1) + buo) ^ la) << 4);
                    uint32_t r0, r1, r2, r3;
                    LDMX4(r0, r1, r2, r3, addr);
                    b[nxt][2*p][0] = r0;   b[nxt][2*p][1] = r1;
                    b[nxt][2*p+1][0] = r2; b[nxt][2*p+1][1] = r3;
                }
            }
            #pragma unroll
            for (int mr = 0; mr < 2; mr++)
                #pragma unroll
                for (int nc = 0; nc < 4; nc++)
                    mma16816(d[mr][nc], a[cur][mr], b[cur][nc]);
        }

        // scoring (proven R15 machinery; cols now cq*32 + nc*8 + 2q)
        #pragma unroll
        for (int mr = 0; mr < 2; mr++)
            #pragma unroll
            for (int h = 0; h < 2; h++) {
                int row = rw*32 + mr*16 + h*8 + g;
                float z2r = z2s[row], cr = crs[row];
                float m = 3.4e38f;
                #pragma unroll
                for (int nc = 0; nc < 4; nc++) {
                    int col = cq*32 + nc*8 + 2*q;
                    float d0 = (z2r + e2c[col])   - d[mr][nc][2*h]*cr;
                    float d1 = (z2r + e2c[col+1]) - d[mr][nc][2*h+1]*cr;
                    m = fminf(m, fminf(d0, d1));
                }
                m = fminf(m, __shfl_xor_sync(0xffffffffu, m, 1));
                m = fminf(m, __shfl_xor_sync(0xffffffffu, m, 2));
                if (q == 0) {
                    float* vp = V + cq*MT + row;     // single writer per slot
                    *vp = fminf(*vp, m);
                }
            }
        __syncwarp();
        #pragma unroll
        for (int mr = 0; mr < 2; mr++)
            #pragma unroll
            for (int h = 0; h < 2; h++) {
                int row = rw*32 + mr*16 + h*8 + g;
                float z2r = z2s[row], cr = crs[row];
                float thr = fminf(fminf(V[row], V[MT + row]),
                                  fminf(V[2*MT + row], V[3*MT + row])) + epss[row];
                #pragma unroll
                for (int nc = 0; nc < 4; nc++)
                    #pragma unroll
                    for (int c01 = 0; c01 < 2; c01++) {
                        int col = cq*32 + nc*8 + 2*q + c01;
                        float dd = (z2r + e2c[col]) - d[mr][nc][2*h+c01]*cr;
                        if (dd <= thr) {
                            int k = cbk*MT + col;
                            int idx = atomicAdd(scnt, 1);
                            if (idx < CAP) {
                                cand[idx] = ((unsigned)row << 16) | (unsigned)k;
                            } else {            // overflow: exact inline (correct, rare)
                                float de = exact_dist(n0 + row, k, z2r, cb);
                                unsigned long long key =
                                    ((unsigned long long)__float_as_uint(de) << 32) | (unsigned)k;
                                atomicMin(best + row, key);
                            }
                        }
                    }
            }
        __syncthreads();
        if (cbk + 2 < NCB) loadB(sb, cbk + 2, t);
    }

    __syncthreads();
    // cooperative exact rescore (proven fp32 pipeline)
    int cnt = *scnt; if (cnt > CAP) cnt = CAP;
    for (int i = t; i < cnt; i += NTHR) {
        unsigned pk = cand[i];
        int row = (int)(pk >> 16), k = (int)(pk & 0xFFFFu);
        float de = exact_dist(n0 + row, k, z2s[row], cb);
        unsigned long long key = ((unsigned long long)__float_as_uint(de) << 32) | (unsigned)k;
        atomicMin(best + row, key);            // positive fp32 bit-monotonic; ties -> smaller k
    }
    __syncthreads();

    float* vmin = crs;                          // reuse
    if (t < MT) {
        unsigned long long kb = best[t];
        int k = (int)(kb & 0xFFFFFFFFull);
        g_idx[n0 + t] = k;
        if (write_idx) out_idx[n0 + t] = (float)k;
        vmin[t] = __uint_as_float((unsigned)(kb >> 32));
    }
    __syncthreads();
    if (t == 0) {
        double s = 0.0;
        for (int r = 0; r < MT; r++) s += (double)vmin[r];
        g_partial[blockIdx.x] = s;              // deterministic
    }
}

// ---------------------------------------------------------------------------
// Kernel D: gather codebook rows by index, write (B, D, HWL)
// ---------------------------------------------------------------------------
__global__ __launch_bounds__(256)
void vq_scatter(const float* __restrict__ cb, float* __restrict__ outq) {
    __shared__ float qt[32*257];
    int b = blockIdx.y, s0 = blockIdx.x << 5, t = threadIdx.x;
    for (int i = t; i < 32*64; i += 256) {
        int r = i >> 6, c4 = i & 63;
        int k = g_idx[b*HWL + s0 + r];
        float4 v = *(const float4*)(cb + (size_t)k*EDIM + (c4 << 2));
        float* dst = qt + r*257 + (c4 << 2);
        dst[0] = v.x; dst[1] = v.y; dst[2] = v.z; dst[3] = v.w;
    }
    __syncthreads();
    int s = t & 31, dh = t >> 5;
    #pragma unroll
    for (int d = dh; d < EDIM; d += 8)
        outq[((size_t)b*EDIM + d)*HWL + s0 + s] = qt[s*257 + d];
}

// ---------------------------------------------------------------------------
// Kernel E: loss = 1.25 * sum(min_dist) / (N*D)
// ---------------------------------------------------------------------------
__global__ void vq_finalize(float* out_loss) {
    double s = 0.0;
    for (int i = 0; i < NBLK; i++) s += g_partial[i];
    *out_loss = (float)(1.25 * s / (double)((size_t)NROWS*EDIM));
}

// ---------------------------------------------------------------------------
extern "C" void kernel_launch(void* const* d_in, const int* in_sizes, int n_in,
                              void* d_out, int out_size) {
    const float* z  = (const float*)d_in[0];
    const float* cb = (const float*)d_in[1];
    if (n_in >= 2 && in_sizes[0] == NEMB*EDIM && in_sizes[1] == NROWS*EDIM) {
        const float* tmp = z; z = cb; cb = tmp;
    }
    float* out = (float*)d_out;

    const int QN = NROWS*EDIM;
    bool has_quant = (out_size >= QN);
    bool full      = (out_size == QN + NROWS + 1);
    float* out_idx  = full ? out + QN         : nullptr;
    float* out_loss = full ? out + QN + NROWS : nullptr;

    cudaFuncSetAttribute(vq_screen, cudaFuncAttributeMaxDynamicSharedMemorySize, SM_TOTAL);

    vq_transpose<<<dim3(HWL/32, EDIM/32, BATCH), dim3(32, 8)>>>(z);
    vq_e2<<<(NEMB + 255)/256, 256>>>(cb);
    vq_packe<<<NEMB/8, 256>>>(cb);
    vq_packz<<<NROWS/32, 256>>>();
    vq_screen<<<NBLK, NTHR, SM_TOTAL>>>(cb, out_idx, full ? 1 : 0);
    if (has_quant)
        vq_scatter<<<dim3(HWL/32, BATCH), 256>>>(cb, out);
    if (full)
        vq_finalize<<<1, 1>>>(out_loss);
}